// round 1
// baseline (speedup 1.0000x reference)
#include <cuda_runtime.h>

// TinyFormerEncoder: B=65536 items, S=16, D=32, FFN=64, fp32.
// Strategy: warp-per-item, all weights in SMEM, packed f32x2 FFMA (Blackwell),
// lane tile = 4 rows x 4 cols so W loads broadcast across 4 rows (crossbar-light).

#define NBLK   1024
#define NTHR   256
#define NWARP  8
#define ITEMS  8      // items per warp: 1024*8*8 = 65536

// ---- per-warp scratch offsets (floats) ----
#define XS_OFF 0        // x / y   [16][33]
#define QS_OFF 528      // q / ctx [16][33]
#define KT_OFF 1056     // k^T     [32][20]
#define VS_OFF 1696     // v       [16][36]
#define SS_OFF 2272     // scores/attn [16][17]
#define HS_OFF 2544     // h       [16][65]
#define WARP_FLOATS 3584

// ---- weight smem offsets (floats) ----
#define WQ_OFF 0
#define WK_OFF 1024
#define WV_OFF 2048
#define WO_OFF 3072
#define W1_OFF 4096
#define W2_OFF 6144
#define BQ_OFF 8192
#define BK_OFF 8224
#define BV_OFF 8256
#define BO_OFF 8288
#define B1_OFF 8320
#define B2_OFF 8384
#define WEIGHT_FLOATS 8416
#define SMEM_FLOATS (WEIGHT_FLOATS + NWARP * WARP_FLOATS)   // 37088 floats = 148352 B

typedef unsigned long long u64;

__device__ __forceinline__ u64 pk2(float a, float b) {
    u64 r; asm("mov.b64 %0, {%1, %2};" : "=l"(r) : "f"(a), "f"(b)); return r;
}
__device__ __forceinline__ void upk2(u64 v, float &a, float &b) {
    asm("mov.b64 {%0, %1}, %2;" : "=f"(a), "=f"(b) : "l"(v));
}
// packed fp32x2 fma: d = a*b + d  (Blackwell FFMA2)
__device__ __forceinline__ void ffma2(u64 &d, u64 a, u64 b) {
    asm("fma.rn.f32x2 %0, %1, %2, %0;" : "+l"(d) : "l"(a), "l"(b));
}

__global__ void __launch_bounds__(NTHR, 1)
tformer_kernel(const float* __restrict__ gx,
               const float* __restrict__ gWq, const float* __restrict__ gbq,
               const float* __restrict__ gWk, const float* __restrict__ gbk,
               const float* __restrict__ gWv, const float* __restrict__ gbv,
               const float* __restrict__ gWo, const float* __restrict__ gbo,
               const float* __restrict__ gW1, const float* __restrict__ gb1,
               const float* __restrict__ gW2, const float* __restrict__ gb2,
               float* __restrict__ gout)
{
    extern __shared__ __align__(16) float sm[];

    // ---- cooperative weight load (cached in L2 across CTAs) ----
    {
        int t = threadIdx.x;
        for (int i = t; i < 1024; i += NTHR) {
            sm[WQ_OFF + i] = gWq[i];
            sm[WK_OFF + i] = gWk[i];
            sm[WV_OFF + i] = gWv[i];
            sm[WO_OFF + i] = gWo[i];
        }
        for (int i = t; i < 2048; i += NTHR) {
            sm[W1_OFF + i] = gW1[i];
            sm[W2_OFF + i] = gW2[i];
        }
        if (t < 32) {
            sm[BQ_OFF + t] = gbq[t];
            sm[BK_OFF + t] = gbk[t];
            sm[BV_OFF + t] = gbv[t];
            sm[BO_OFF + t] = gbo[t];
            sm[B2_OFF + t] = gb2[t];
        }
        if (t < 64) sm[B1_OFF + t] = gb1[t];
    }
    __syncthreads();

    const int warp = threadIdx.x >> 5;
    const int lane = threadIdx.x & 31;
    const int g    = lane >> 3;     // row group: rows 4g..4g+3
    const int m    = lane & 7;
    const int c4   = m * 4;         // col base for 32-wide outputs
    const int c8   = m * 8;         // col base for 64-wide outputs

    float* xs = sm + WEIGHT_FLOATS + warp * WARP_FLOATS + XS_OFF;
    float* qs = sm + WEIGHT_FLOATS + warp * WARP_FLOATS + QS_OFF;
    float* kT = sm + WEIGHT_FLOATS + warp * WARP_FLOATS + KT_OFF;
    float* vs = sm + WEIGHT_FLOATS + warp * WARP_FLOATS + VS_OFF;
    float* ss = sm + WEIGHT_FLOATS + warp * WARP_FLOATS + SS_OFF;
    float* hs = sm + WEIGHT_FLOATS + warp * WARP_FLOATS + HS_OFF;

    const int wglob = blockIdx.x * NWARP + warp;

    for (int it = 0; it < ITEMS; ++it) {
        const int b = wglob * ITEMS + it;
        const float* xb = gx + (size_t)b * 512;

        // ---- load x [16][32] -> xs (padded ld=33), coalesced float4 ----
        #pragma unroll
        for (int i = 0; i < 4; ++i) {
            float4 v = reinterpret_cast<const float4*>(xb)[lane + 32 * i];
            int e = (lane + 32 * i) * 4;
            int r = e >> 5, c = e & 31;
            float* p = xs + r * 33 + c;
            p[0] = v.x; p[1] = v.y; p[2] = v.z; p[3] = v.w;
        }
        __syncwarp();

        // ================= fused Q, K, V projections =================
        u64 aq[8], ak[8], av[8];
        {
            ulonglong2 b_q = *reinterpret_cast<const ulonglong2*>(sm + BQ_OFF + c4);
            ulonglong2 b_k = *reinterpret_cast<const ulonglong2*>(sm + BK_OFF + c4);
            ulonglong2 b_v = *reinterpret_cast<const ulonglong2*>(sm + BV_OFF + c4);
            #pragma unroll
            for (int i = 0; i < 4; ++i) {
                aq[i*2] = b_q.x; aq[i*2+1] = b_q.y;
                ak[i*2] = b_k.x; ak[i*2+1] = b_k.y;
                av[i*2] = b_v.x; av[i*2+1] = b_v.y;
            }
        }
        #pragma unroll 4
        for (int k = 0; k < 32; ++k) {
            u64 xx[4];
            #pragma unroll
            for (int i = 0; i < 4; ++i) {
                float xv = xs[(4*g + i) * 33 + k];
                xx[i] = pk2(xv, xv);
            }
            ulonglong2 wq = *reinterpret_cast<const ulonglong2*>(sm + WQ_OFF + k*32 + c4);
            ulonglong2 wk = *reinterpret_cast<const ulonglong2*>(sm + WK_OFF + k*32 + c4);
            ulonglong2 wv = *reinterpret_cast<const ulonglong2*>(sm + WV_OFF + k*32 + c4);
            #pragma unroll
            for (int i = 0; i < 4; ++i) {
                ffma2(aq[i*2],   xx[i], wq.x); ffma2(aq[i*2+1], xx[i], wq.y);
                ffma2(ak[i*2],   xx[i], wk.x); ffma2(ak[i*2+1], xx[i], wk.y);
                ffma2(av[i*2],   xx[i], wv.x); ffma2(av[i*2+1], xx[i], wv.y);
            }
        }
        {
            const float QSC = 0.17677669529663687f;  // 1/sqrt(D), folded into q
            #pragma unroll
            for (int i = 0; i < 4; ++i) {
                int r = 4*g + i;
                #pragma unroll
                for (int p = 0; p < 2; ++p) {
                    float lo, hi;
                    upk2(aq[i*2+p], lo, hi);
                    qs[r*33 + c4 + 2*p]     = lo * QSC;
                    qs[r*33 + c4 + 2*p + 1] = hi * QSC;
                    upk2(ak[i*2+p], lo, hi);
                    kT[(c4 + 2*p    ) * 20 + r] = lo;     // transposed K store
                    kT[(c4 + 2*p + 1) * 20 + r] = hi;
                    upk2(av[i*2+p], lo, hi);
                    vs[r*36 + c4 + 2*p]     = lo;
                    vs[r*36 + c4 + 2*p + 1] = hi;
                }
            }
        }
        __syncwarp();

        // ================= scores = q_scaled . k =================
        u64 as_[4] = {0ull, 0ull, 0ull, 0ull};
        #pragma unroll 4
        for (int d = 0; d < 32; ++d) {
            u64 kk = *reinterpret_cast<const u64*>(kT + d*20 + 2*m);
            #pragma unroll
            for (int i = 0; i < 4; ++i) {
                float qv = qs[(4*g + i) * 33 + d];
                ffma2(as_[i], pk2(qv, qv), kk);
            }
        }
        // ---- softmax over each row (8 lanes per row via shfl_xor 1/2/4) ----
        #pragma unroll
        for (int i = 0; i < 4; ++i) {
            float lo, hi; upk2(as_[i], lo, hi);
            float mx = fmaxf(lo, hi);
            #pragma unroll
            for (int o = 1; o < 8; o <<= 1)
                mx = fmaxf(mx, __shfl_xor_sync(0xffffffffu, mx, o));
            float e0 = __expf(lo - mx), e1 = __expf(hi - mx);
            float s = e0 + e1;
            #pragma unroll
            for (int o = 1; o < 8; o <<= 1)
                s += __shfl_xor_sync(0xffffffffu, s, o);
            float rs = __fdividef(1.0f, s);
            ss[(4*g + i) * 17 + 2*m]     = e0 * rs;
            ss[(4*g + i) * 17 + 2*m + 1] = e1 * rs;
        }
        __syncwarp();

        // ================= context = attn @ V  (-> qs, reused) =================
        u64 ac[8];
        #pragma unroll
        for (int i = 0; i < 8; ++i) ac[i] = 0ull;
        #pragma unroll 4
        for (int t = 0; t < 16; ++t) {
            ulonglong2 vv = *reinterpret_cast<const ulonglong2*>(vs + t*36 + c4);
            #pragma unroll
            for (int i = 0; i < 4; ++i) {
                float a = ss[(4*g + i) * 17 + t];
                u64 aa = pk2(a, a);
                ffma2(ac[i*2], aa, vv.x); ffma2(ac[i*2+1], aa, vv.y);
            }
        }
        #pragma unroll
        for (int i = 0; i < 4; ++i) {
            int r = 4*g + i;
            float lo, hi;
            upk2(ac[i*2],   lo, hi); qs[r*33 + c4]     = lo; qs[r*33 + c4 + 1] = hi;
            upk2(ac[i*2+1], lo, hi); qs[r*33 + c4 + 2] = lo; qs[r*33 + c4 + 3] = hi;
        }
        __syncwarp();

        // ================= y = x + ctx @ Wo + bo  (-> xs) =================
        u64 ay[8];
        {
            ulonglong2 b_o = *reinterpret_cast<const ulonglong2*>(sm + BO_OFF + c4);
            #pragma unroll
            for (int i = 0; i < 4; ++i) { ay[i*2] = b_o.x; ay[i*2+1] = b_o.y; }
        }
        #pragma unroll 4
        for (int k = 0; k < 32; ++k) {
            ulonglong2 w = *reinterpret_cast<const ulonglong2*>(sm + WO_OFF + k*32 + c4);
            #pragma unroll
            for (int i = 0; i < 4; ++i) {
                float cv = qs[(4*g + i) * 33 + k];
                u64 cc = pk2(cv, cv);
                ffma2(ay[i*2], cc, w.x); ffma2(ay[i*2+1], cc, w.y);
            }
        }
        #pragma unroll
        for (int i = 0; i < 4; ++i) {
            int r = 4*g + i;
            float lo, hi;
            upk2(ay[i*2], lo, hi);
            xs[r*33 + c4]     = lo + xs[r*33 + c4];
            xs[r*33 + c4 + 1] = hi + xs[r*33 + c4 + 1];
            upk2(ay[i*2+1], lo, hi);
            xs[r*33 + c4 + 2] = lo + xs[r*33 + c4 + 2];
            xs[r*33 + c4 + 3] = hi + xs[r*33 + c4 + 3];
        }
        __syncwarp();

        // ================= h = relu(y @ W1 + b1)  (-> hs) =================
        u64 ah[16];
        {
            ulonglong2 b1a = *reinterpret_cast<const ulonglong2*>(sm + B1_OFF + c8);
            ulonglong2 b1b = *reinterpret_cast<const ulonglong2*>(sm + B1_OFF + c8 + 4);
            #pragma unroll
            for (int i = 0; i < 4; ++i) {
                ah[i*4]   = b1a.x; ah[i*4+1] = b1a.y;
                ah[i*4+2] = b1b.x; ah[i*4+3] = b1b.y;
            }
        }
        #pragma unroll 4
        for (int k = 0; k < 32; ++k) {
            u64 xx[4];
            #pragma unroll
            for (int i = 0; i < 4; ++i) {
                float yv = xs[(4*g + i) * 33 + k];
                xx[i] = pk2(yv, yv);
            }
            ulonglong2 w1a = *reinterpret_cast<const ulonglong2*>(sm + W1_OFF + k*64 + c8);
            ulonglong2 w1b = *reinterpret_cast<const ulonglong2*>(sm + W1_OFF + k*64 + c8 + 4);
            #pragma unroll
            for (int i = 0; i < 4; ++i) {
                ffma2(ah[i*4],   xx[i], w1a.x); ffma2(ah[i*4+1], xx[i], w1a.y);
                ffma2(ah[i*4+2], xx[i], w1b.x); ffma2(ah[i*4+3], xx[i], w1b.y);
            }
        }
        #pragma unroll
        for (int i = 0; i < 4; ++i) {
            int r = 4*g + i;
            #pragma unroll
            for (int j = 0; j < 4; ++j) {
                float lo, hi; upk2(ah[i*4+j], lo, hi);
                hs[r*65 + c8 + 2*j]     = fmaxf(lo, 0.0f);
                hs[r*65 + c8 + 2*j + 1] = fmaxf(hi, 0.0f);
            }
        }
        __syncwarp();

        // ================= z = y + h @ W2 + b2  (-> gmem) =================
        u64 az[8];
        {
            ulonglong2 b_2 = *reinterpret_cast<const ulonglong2*>(sm + B2_OFF + c4);
            #pragma unroll
            for (int i = 0; i < 4; ++i) { az[i*2] = b_2.x; az[i*2+1] = b_2.y; }
        }
        #pragma unroll 4
        for (int k = 0; k < 64; ++k) {
            u64 xx[4];
            #pragma unroll
            for (int i = 0; i < 4; ++i) {
                float hv = hs[(4*g + i) * 65 + k];
                xx[i] = pk2(hv, hv);
            }
            ulonglong2 w = *reinterpret_cast<const ulonglong2*>(sm + W2_OFF + k*32 + c4);
            #pragma unroll
            for (int i = 0; i < 4; ++i) {
                ffma2(az[i*2], xx[i], w.x); ffma2(az[i*2+1], xx[i], w.y);
            }
        }
        {
            float* ob = gout + (size_t)b * 512;
            #pragma unroll
            for (int i = 0; i < 4; ++i) {
                int r = 4*g + i;
                float z0, z1, z2, z3;
                upk2(az[i*2],   z0, z1);
                upk2(az[i*2+1], z2, z3);
                const float* yr = xs + r*33 + c4;
                float4 o;
                o.x = z0 + yr[0]; o.y = z1 + yr[1];
                o.z = z2 + yr[2]; o.w = z3 + yr[3];
                *reinterpret_cast<float4*>(ob + r*32 + c4) = o;
            }
        }
        __syncwarp();   // protect xs/hs before next item's overwrite
    }
}

extern "C" void kernel_launch(void* const* d_in, const int* in_sizes, int n_in,
                              void* d_out, int out_size)
{
    const float* x  = (const float*)d_in[0];
    const float* Wq = (const float*)d_in[1];
    const float* bq = (const float*)d_in[2];
    const float* Wk = (const float*)d_in[3];
    const float* bk = (const float*)d_in[4];
    const float* Wv = (const float*)d_in[5];
    const float* bv = (const float*)d_in[6];
    const float* Wo = (const float*)d_in[7];
    const float* bo = (const float*)d_in[8];
    const float* W1 = (const float*)d_in[9];
    const float* b1 = (const float*)d_in[10];
    const float* W2 = (const float*)d_in[11];
    const float* b2 = (const float*)d_in[12];
    float* out = (float*)d_out;

    const size_t smem = SMEM_FLOATS * sizeof(float);  // 148352 B
    cudaFuncSetAttribute(tformer_kernel,
                         cudaFuncAttributeMaxDynamicSharedMemorySize, (int)smem);

    tformer_kernel<<<NBLK, NTHR, smem>>>(x, Wq, bq, Wk, bk, Wv, bv, Wo, bo,
                                         W1, b1, W2, b2, out);
}

// round 2
// speedup vs baseline: 1.0926x; 1.0926x over previous
#include <cuda_runtime.h>

// TinyFormerEncoder: B=65536 items, S=16, D=32, FFN=64, fp32.
// R2: vectorized activation feeds (LDS.128 row loads instead of scalar
// broadcast), no transposed-K, 192thr/CTA x 2 CTAs/SM for 12 warps/SM.

#define BTOT   65536
#define NTHR   192
#define NWARP  6
#define ITEMS  8
#define NBLK   1366   // ceil(65536 / (6*8))

// ---- per-warp scratch (floats) ----
#define XST 36
#define QST 36
#define KST 36
#define VST 36
#define SST 20
#define HST 68
#define XS_OFF 0      // x, later y      [16][36]
#define QS_OFF 576    // q, later ctx    [16][36]
#define KS_OFF 1152   // k               [16][36]
#define VS_OFF 1728   // v               [16][36]
#define SS_OFF 2304   // attn            [16][20]
#define HS_OFF 1152   // h [16][68]=1088, aliases ks+vs (dead by then)
#define WARP_FLOATS 2624

// ---- weight smem (floats) ----
#define WQ_OFF 0
#define WK_OFF 1024
#define WV_OFF 2048
#define WO_OFF 3072
#define W1_OFF 4096
#define W2_OFF 6144
#define BQ_OFF 8192
#define BK_OFF 8224
#define BV_OFF 8256
#define BO_OFF 8288
#define B1_OFF 8320
#define B2_OFF 8384
#define WEIGHT_FLOATS 8416
#define SMEM_FLOATS (WEIGHT_FLOATS + NWARP * WARP_FLOATS)  // 24160 fl = 96640 B

typedef unsigned long long u64;

__device__ __forceinline__ u64 pk2(float a, float b) {
    u64 r; asm("mov.b64 %0, {%1, %2};" : "=l"(r) : "f"(a), "f"(b)); return r;
}
__device__ __forceinline__ void upk2(u64 v, float &a, float &b) {
    asm("mov.b64 {%0, %1}, %2;" : "=f"(a), "=f"(b) : "l"(v));
}
__device__ __forceinline__ void ffma2(u64 &d, u64 a, u64 b) {
    asm("fma.rn.f32x2 %0, %1, %2, %0;" : "+l"(d) : "l"(a), "l"(b));
}
__device__ __forceinline__ float f4c(const float4 &v, int j) {
    return (&v.x)[j];
}

__global__ void __launch_bounds__(NTHR, 2)
tformer_kernel(const float* __restrict__ gx,
               const float* __restrict__ gWq, const float* __restrict__ gbq,
               const float* __restrict__ gWk, const float* __restrict__ gbk,
               const float* __restrict__ gWv, const float* __restrict__ gbv,
               const float* __restrict__ gWo, const float* __restrict__ gbo,
               const float* __restrict__ gW1, const float* __restrict__ gb1,
               const float* __restrict__ gW2, const float* __restrict__ gb2,
               float* __restrict__ gout)
{
    extern __shared__ __align__(16) float sm[];

    {   // cooperative weight load
        int t = threadIdx.x;
        for (int i = t; i < 1024; i += NTHR) {
            sm[WQ_OFF + i] = gWq[i];
            sm[WK_OFF + i] = gWk[i];
            sm[WV_OFF + i] = gWv[i];
            sm[WO_OFF + i] = gWo[i];
        }
        for (int i = t; i < 2048; i += NTHR) {
            sm[W1_OFF + i] = gW1[i];
            sm[W2_OFF + i] = gW2[i];
        }
        if (t < 32) {
            sm[BQ_OFF + t] = gbq[t];
            sm[BK_OFF + t] = gbk[t];
            sm[BV_OFF + t] = gbv[t];
            sm[BO_OFF + t] = gbo[t];
            sm[B2_OFF + t] = gb2[t];
        }
        if (t < 64) sm[B1_OFF + t] = gb1[t];
    }
    __syncthreads();

    const int warp = threadIdx.x / 32;
    const int lane = threadIdx.x & 31;
    const int g    = lane >> 3;      // row group: rows 4g..4g+3
    const int m    = lane & 7;
    const int c4   = m * 4;
    const int c8   = m * 8;

    float* xs = sm + WEIGHT_FLOATS + warp * WARP_FLOATS + XS_OFF;
    float* qs = sm + WEIGHT_FLOATS + warp * WARP_FLOATS + QS_OFF;
    float* ks = sm + WEIGHT_FLOATS + warp * WARP_FLOATS + KS_OFF;
    float* vs = sm + WEIGHT_FLOATS + warp * WARP_FLOATS + VS_OFF;
    float* ss = sm + WEIGHT_FLOATS + warp * WARP_FLOATS + SS_OFF;
    float* hs = sm + WEIGHT_FLOATS + warp * WARP_FLOATS + HS_OFF;

    const int wglob = blockIdx.x * NWARP + warp;

    for (int it = 0; it < ITEMS; ++it) {
        const int b = wglob * ITEMS + it;
        if (b >= BTOT) break;
        const float* xb = gx + (size_t)b * 512;

        // ---- load x [16][32] -> xs (stride 36), coalesced float4 ----
        #pragma unroll
        for (int i = 0; i < 4; ++i) {
            float4 v = reinterpret_cast<const float4*>(xb)[lane + 32 * i];
            int e = (lane + 32 * i) * 4;
            int r = e >> 5, c = e & 31;
            *reinterpret_cast<float4*>(xs + r * XST + c) = v;
        }
        __syncwarp();

        // ================= fused Q, K, V projections =================
        u64 aq[8], ak[8], av[8];
        {
            ulonglong2 b_q = *reinterpret_cast<const ulonglong2*>(sm + BQ_OFF + c4);
            ulonglong2 b_k = *reinterpret_cast<const ulonglong2*>(sm + BK_OFF + c4);
            ulonglong2 b_v = *reinterpret_cast<const ulonglong2*>(sm + BV_OFF + c4);
            #pragma unroll
            for (int i = 0; i < 4; ++i) {
                aq[i*2] = b_q.x; aq[i*2+1] = b_q.y;
                ak[i*2] = b_k.x; ak[i*2+1] = b_k.y;
                av[i*2] = b_v.x; av[i*2+1] = b_v.y;
            }
        }
        #pragma unroll
        for (int kb = 0; kb < 8; ++kb) {
            float4 xr[4];
            #pragma unroll
            for (int i = 0; i < 4; ++i)
                xr[i] = *reinterpret_cast<const float4*>(xs + (4*g + i) * XST + kb*4);
            #pragma unroll
            for (int j = 0; j < 4; ++j) {
                int k = kb*4 + j;
                ulonglong2 wq = *reinterpret_cast<const ulonglong2*>(sm + WQ_OFF + k*32 + c4);
                ulonglong2 wk = *reinterpret_cast<const ulonglong2*>(sm + WK_OFF + k*32 + c4);
                ulonglong2 wv = *reinterpret_cast<const ulonglong2*>(sm + WV_OFF + k*32 + c4);
                #pragma unroll
                for (int i = 0; i < 4; ++i) {
                    float xv = f4c(xr[i], j);
                    u64 xx = pk2(xv, xv);
                    ffma2(aq[i*2], xx, wq.x); ffma2(aq[i*2+1], xx, wq.y);
                    ffma2(ak[i*2], xx, wk.x); ffma2(ak[i*2+1], xx, wk.y);
                    ffma2(av[i*2], xx, wv.x); ffma2(av[i*2+1], xx, wv.y);
                }
            }
        }
        {
            const float QSC = 0.17677669529663687f;  // 1/sqrt(D) folded into q
            #pragma unroll
            for (int i = 0; i < 4; ++i) {
                int r = 4*g + i;
                float a0, a1, a2, a3;
                upk2(aq[i*2], a0, a1); upk2(aq[i*2+1], a2, a3);
                *reinterpret_cast<float4*>(qs + r*QST + c4) =
                    make_float4(a0*QSC, a1*QSC, a2*QSC, a3*QSC);
                upk2(ak[i*2], a0, a1); upk2(ak[i*2+1], a2, a3);
                *reinterpret_cast<float4*>(ks + r*KST + c4) =
                    make_float4(a0, a1, a2, a3);
                upk2(av[i*2], a0, a1); upk2(av[i*2+1], a2, a3);
                *reinterpret_cast<float4*>(vs + r*VST + c4) =
                    make_float4(a0, a1, a2, a3);
            }
        }
        __syncwarp();

        // ===== scores[r][2m,2m+1] = q[r] . k[2m], q[r] . k[2m+1] =====
        u64 as_[4] = {0ull, 0ull, 0ull, 0ull};
        #pragma unroll
        for (int db = 0; db < 8; ++db) {
            float4 qr[4];
            #pragma unroll
            for (int i = 0; i < 4; ++i)
                qr[i] = *reinterpret_cast<const float4*>(qs + (4*g + i) * QST + db*4);
            float4 k0 = *reinterpret_cast<const float4*>(ks + (2*m    ) * KST + db*4);
            float4 k1 = *reinterpret_cast<const float4*>(ks + (2*m + 1) * KST + db*4);
            #pragma unroll
            for (int j = 0; j < 4; ++j) {
                u64 kk = pk2(f4c(k0, j), f4c(k1, j));
                #pragma unroll
                for (int i = 0; i < 4; ++i) {
                    float qv = f4c(qr[i], j);
                    ffma2(as_[i], pk2(qv, qv), kk);
                }
            }
        }
        // ---- softmax per row (8 m-lanes per row hold 16 scores) ----
        #pragma unroll
        for (int i = 0; i < 4; ++i) {
            float lo, hi; upk2(as_[i], lo, hi);
            float mx = fmaxf(lo, hi);
            #pragma unroll
            for (int o = 1; o < 8; o <<= 1)
                mx = fmaxf(mx, __shfl_xor_sync(0xffffffffu, mx, o));
            float e0 = __expf(lo - mx), e1 = __expf(hi - mx);
            float s = e0 + e1;
            #pragma unroll
            for (int o = 1; o < 8; o <<= 1)
                s += __shfl_xor_sync(0xffffffffu, s, o);
            float rs = __fdividef(1.0f, s);
            *reinterpret_cast<float2*>(ss + (4*g + i) * SST + 2*m) =
                make_float2(e0 * rs, e1 * rs);
        }
        __syncwarp();

        // ================= context = attn @ V  (-> qs) =================
        u64 ac[8];
        #pragma unroll
        for (int i = 0; i < 8; ++i) ac[i] = 0ull;
        #pragma unroll
        for (int tb = 0; tb < 4; ++tb) {
            float4 ar[4];
            #pragma unroll
            for (int i = 0; i < 4; ++i)
                ar[i] = *reinterpret_cast<const float4*>(ss + (4*g + i) * SST + tb*4);
            #pragma unroll
            for (int j = 0; j < 4; ++j) {
                int t = tb*4 + j;
                ulonglong2 vv = *reinterpret_cast<const ulonglong2*>(vs + t*VST + c4);
                #pragma unroll
                for (int i = 0; i < 4; ++i) {
                    float a = f4c(ar[i], j);
                    u64 aa = pk2(a, a);
                    ffma2(ac[i*2], aa, vv.x); ffma2(ac[i*2+1], aa, vv.y);
                }
            }
        }
        #pragma unroll
        for (int i = 0; i < 4; ++i) {
            int r = 4*g + i;
            float a0, a1, a2, a3;
            upk2(ac[i*2], a0, a1); upk2(ac[i*2+1], a2, a3);
            *reinterpret_cast<float4*>(qs + r*QST + c4) = make_float4(a0, a1, a2, a3);
        }
        __syncwarp();

        // ================= y = x + ctx @ Wo + bo  (-> xs) =================
        u64 ay[8];
        {
            ulonglong2 b_o = *reinterpret_cast<const ulonglong2*>(sm + BO_OFF + c4);
            #pragma unroll
            for (int i = 0; i < 4; ++i) { ay[i*2] = b_o.x; ay[i*2+1] = b_o.y; }
        }
        #pragma unroll
        for (int kb = 0; kb < 8; ++kb) {
            float4 cr[4];
            #pragma unroll
            for (int i = 0; i < 4; ++i)
                cr[i] = *reinterpret_cast<const float4*>(qs + (4*g + i) * QST + kb*4);
            #pragma unroll
            for (int j = 0; j < 4; ++j) {
                int k = kb*4 + j;
                ulonglong2 w = *reinterpret_cast<const ulonglong2*>(sm + WO_OFF + k*32 + c4);
                #pragma unroll
                for (int i = 0; i < 4; ++i) {
                    float cv = f4c(cr[i], j);
                    u64 cc = pk2(cv, cv);
                    ffma2(ay[i*2], cc, w.x); ffma2(ay[i*2+1], cc, w.y);
                }
            }
        }
        #pragma unroll
        for (int i = 0; i < 4; ++i) {
            int r = 4*g + i;
            float4 x4 = *reinterpret_cast<const float4*>(xs + r*XST + c4);
            float a0, a1, a2, a3;
            upk2(ay[i*2], a0, a1); upk2(ay[i*2+1], a2, a3);
            *reinterpret_cast<float4*>(xs + r*XST + c4) =
                make_float4(a0 + x4.x, a1 + x4.y, a2 + x4.z, a3 + x4.w);
        }
        __syncwarp();

        // ================= h = relu(y @ W1 + b1)  (-> hs) =================
        u64 ah[16];
        {
            ulonglong2 b1a = *reinterpret_cast<const ulonglong2*>(sm + B1_OFF + c8);
            ulonglong2 b1b = *reinterpret_cast<const ulonglong2*>(sm + B1_OFF + c8 + 4);
            #pragma unroll
            for (int i = 0; i < 4; ++i) {
                ah[i*4]   = b1a.x; ah[i*4+1] = b1a.y;
                ah[i*4+2] = b1b.x; ah[i*4+3] = b1b.y;
            }
        }
        #pragma unroll
        for (int kb = 0; kb < 8; ++kb) {
            float4 yr[4];
            #pragma unroll
            for (int i = 0; i < 4; ++i)
                yr[i] = *reinterpret_cast<const float4*>(xs + (4*g + i) * XST + kb*4);
            #pragma unroll
            for (int j = 0; j < 4; ++j) {
                int k = kb*4 + j;
                ulonglong2 w1a = *reinterpret_cast<const ulonglong2*>(sm + W1_OFF + k*64 + c8);
                ulonglong2 w1b = *reinterpret_cast<const ulonglong2*>(sm + W1_OFF + k*64 + c8 + 4);
                #pragma unroll
                for (int i = 0; i < 4; ++i) {
                    float yv = f4c(yr[i], j);
                    u64 xx = pk2(yv, yv);
                    ffma2(ah[i*4],   xx, w1a.x); ffma2(ah[i*4+1], xx, w1a.y);
                    ffma2(ah[i*4+2], xx, w1b.x); ffma2(ah[i*4+3], xx, w1b.y);
                }
            }
        }
        #pragma unroll
        for (int i = 0; i < 4; ++i) {
            int r = 4*g + i;
            float a0, a1, a2, a3, a4, a5, a6, a7;
            upk2(ah[i*4],   a0, a1); upk2(ah[i*4+1], a2, a3);
            upk2(ah[i*4+2], a4, a5); upk2(ah[i*4+3], a6, a7);
            *reinterpret_cast<float4*>(hs + r*HST + c8) =
                make_float4(fmaxf(a0,0.f), fmaxf(a1,0.f), fmaxf(a2,0.f), fmaxf(a3,0.f));
            *reinterpret_cast<float4*>(hs + r*HST + c8 + 4) =
                make_float4(fmaxf(a4,0.f), fmaxf(a5,0.f), fmaxf(a6,0.f), fmaxf(a7,0.f));
        }
        __syncwarp();

        // ================= z = y + h @ W2 + b2  (-> gmem) =================
        u64 az[8];
        {
            ulonglong2 b_2 = *reinterpret_cast<const ulonglong2*>(sm + B2_OFF + c4);
            #pragma unroll
            for (int i = 0; i < 4; ++i) { az[i*2] = b_2.x; az[i*2+1] = b_2.y; }
        }
        #pragma unroll
        for (int kb = 0; kb < 16; ++kb) {
            float4 hr[4];
            #pragma unroll
            for (int i = 0; i < 4; ++i)
                hr[i] = *reinterpret_cast<const float4*>(hs + (4*g + i) * HST + kb*4);
            #pragma unroll
            for (int j = 0; j < 4; ++j) {
                int k = kb*4 + j;
                ulonglong2 w = *reinterpret_cast<const ulonglong2*>(sm + W2_OFF + k*32 + c4);
                #pragma unroll
                for (int i = 0; i < 4; ++i) {
                    float hv = f4c(hr[i], j);
                    u64 hh = pk2(hv, hv);
                    ffma2(az[i*2], hh, w.x); ffma2(az[i*2+1], hh, w.y);
                }
            }
        }
        {
            float* ob = gout + (size_t)b * 512;
            #pragma unroll
            for (int i = 0; i < 4; ++i) {
                int r = 4*g + i;
                float4 yr = *reinterpret_cast<const float4*>(xs + r*XST + c4);
                float z0, z1, z2, z3;
                upk2(az[i*2], z0, z1); upk2(az[i*2+1], z2, z3);
                float4 o;
                o.x = z0 + yr.x; o.y = z1 + yr.y; o.z = z2 + yr.z; o.w = z3 + yr.w;
                *reinterpret_cast<float4*>(ob + r*32 + c4) = o;
            }
        }
        __syncwarp();   // protect scratch before next item's overwrite
    }
}

extern "C" void kernel_launch(void* const* d_in, const int* in_sizes, int n_in,
                              void* d_out, int out_size)
{
    const float* x  = (const float*)d_in[0];
    const float* Wq = (const float*)d_in[1];
    const float* bq = (const float*)d_in[2];
    const float* Wk = (const float*)d_in[3];
    const float* bk = (const float*)d_in[4];
    const float* Wv = (const float*)d_in[5];
    const float* bv = (const float*)d_in[6];
    const float* Wo = (const float*)d_in[7];
    const float* bo = (const float*)d_in[8];
    const float* W1 = (const float*)d_in[9];
    const float* b1 = (const float*)d_in[10];
    const float* W2 = (const float*)d_in[11];
    const float* b2 = (const float*)d_in[12];
    float* out = (float*)d_out;

    const size_t smem = SMEM_FLOATS * sizeof(float);  // 96640 B
    cudaFuncSetAttribute(tformer_kernel,
                         cudaFuncAttributeMaxDynamicSharedMemorySize, (int)smem);

    tformer_kernel<<<NBLK, NTHR, smem>>>(x, Wq, bq, Wk, bk, Wv, bv, Wo, bo,
                                         W1, b1, W2, b2, out);
}

// round 3
// speedup vs baseline: 1.0950x; 1.0022x over previous
#include <cuda_runtime.h>

// TinyFormerEncoder: B=65536 items, S=16, D=32, FFN=64, fp32.
// R2: vectorized activation feeds (LDS.128 row loads instead of scalar
// broadcast), no transposed-K, 192thr/CTA x 2 CTAs/SM for 12 warps/SM.

#define BTOT   65536
#define NTHR   192
#define NWARP  6
#define ITEMS  8
#define NBLK   1366   // ceil(65536 / (6*8))

// ---- per-warp scratch (floats) ----
#define XST 36
#define QST 36
#define KST 36
#define VST 36
#define SST 20
#define HST 68
#define XS_OFF 0      // x, later y      [16][36]
#define QS_OFF 576    // q, later ctx    [16][36]
#define KS_OFF 1152   // k               [16][36]
#define VS_OFF 1728   // v               [16][36]
#define SS_OFF 2304   // attn            [16][20]
#define HS_OFF 1152   // h [16][68]=1088, aliases ks+vs (dead by then)
#define WARP_FLOATS 2624

// ---- weight smem (floats) ----
#define WQ_OFF 0
#define WK_OFF 1024
#define WV_OFF 2048
#define WO_OFF 3072
#define W1_OFF 4096
#define W2_OFF 6144
#define BQ_OFF 8192
#define BK_OFF 8224
#define BV_OFF 8256
#define BO_OFF 8288
#define B1_OFF 8320
#define B2_OFF 8384
#define WEIGHT_FLOATS 8416
#define SMEM_FLOATS (WEIGHT_FLOATS + NWARP * WARP_FLOATS)  // 24160 fl = 96640 B

typedef unsigned long long u64;

__device__ __forceinline__ u64 pk2(float a, float b) {
    u64 r; asm("mov.b64 %0, {%1, %2};" : "=l"(r) : "f"(a), "f"(b)); return r;
}
__device__ __forceinline__ void upk2(u64 v, float &a, float &b) {
    asm("mov.b64 {%0, %1}, %2;" : "=f"(a), "=f"(b) : "l"(v));
}
__device__ __forceinline__ void ffma2(u64 &d, u64 a, u64 b) {
    asm("fma.rn.f32x2 %0, %1, %2, %0;" : "+l"(d) : "l"(a), "l"(b));
}
__device__ __forceinline__ float f4c(const float4 &v, int j) {
    return (&v.x)[j];
}

__global__ void __launch_bounds__(NTHR, 2)
tformer_kernel(const float* __restrict__ gx,
               const float* __restrict__ gWq, const float* __restrict__ gbq,
               const float* __restrict__ gWk, const float* __restrict__ gbk,
               const float* __restrict__ gWv, const float* __restrict__ gbv,
               const float* __restrict__ gWo, const float* __restrict__ gbo,
               const float* __restrict__ gW1, const float* __restrict__ gb1,
               const float* __restrict__ gW2, const float* __restrict__ gb2,
               float* __restrict__ gout)
{
    extern __shared__ __align__(16) float sm[];

    {   // cooperative weight load
        int t = threadIdx.x;
        for (int i = t; i < 1024; i += NTHR) {
            sm[WQ_OFF + i] = gWq[i];
            sm[WK_OFF + i] = gWk[i];
            sm[WV_OFF + i] = gWv[i];
            sm[WO_OFF + i] = gWo[i];
        }
        for (int i = t; i < 2048; i += NTHR) {
            sm[W1_OFF + i] = gW1[i];
            sm[W2_OFF + i] = gW2[i];
        }
        if (t < 32) {
            sm[BQ_OFF + t] = gbq[t];
            sm[BK_OFF + t] = gbk[t];
            sm[BV_OFF + t] = gbv[t];
            sm[BO_OFF + t] = gbo[t];
            sm[B2_OFF + t] = gb2[t];
        }
        if (t < 64) sm[B1_OFF + t] = gb1[t];
    }
    __syncthreads();

    const int warp = threadIdx.x / 32;
    const int lane = threadIdx.x & 31;
    const int g    = lane >> 3;      // row group: rows 4g..4g+3
    const int m    = lane & 7;
    const int c4   = m * 4;
    const int c8   = m * 8;

    float* xs = sm + WEIGHT_FLOATS + warp * WARP_FLOATS + XS_OFF;
    float* qs = sm + WEIGHT_FLOATS + warp * WARP_FLOATS + QS_OFF;
    float* ks = sm + WEIGHT_FLOATS + warp * WARP_FLOATS + KS_OFF;
    float* vs = sm + WEIGHT_FLOATS + warp * WARP_FLOATS + VS_OFF;
    float* ss = sm + WEIGHT_FLOATS + warp * WARP_FLOATS + SS_OFF;
    float* hs = sm + WEIGHT_FLOATS + warp * WARP_FLOATS + HS_OFF;

    const int wglob = blockIdx.x * NWARP + warp;

    for (int it = 0; it < ITEMS; ++it) {
        const int b = wglob * ITEMS + it;
        if (b >= BTOT) break;
        const float* xb = gx + (size_t)b * 512;

        // ---- load x [16][32] -> xs (stride 36), coalesced float4 ----
        #pragma unroll
        for (int i = 0; i < 4; ++i) {
            float4 v = reinterpret_cast<const float4*>(xb)[lane + 32 * i];
            int e = (lane + 32 * i) * 4;
            int r = e >> 5, c = e & 31;
            *reinterpret_cast<float4*>(xs + r * XST + c) = v;
        }
        __syncwarp();

        // ================= fused Q, K, V projections =================
        u64 aq[8], ak[8], av[8];
        {
            ulonglong2 b_q = *reinterpret_cast<const ulonglong2*>(sm + BQ_OFF + c4);
            ulonglong2 b_k = *reinterpret_cast<const ulonglong2*>(sm + BK_OFF + c4);
            ulonglong2 b_v = *reinterpret_cast<const ulonglong2*>(sm + BV_OFF + c4);
            #pragma unroll
            for (int i = 0; i < 4; ++i) {
                aq[i*2] = b_q.x; aq[i*2+1] = b_q.y;
                ak[i*2] = b_k.x; ak[i*2+1] = b_k.y;
                av[i*2] = b_v.x; av[i*2+1] = b_v.y;
            }
        }
        #pragma unroll
        for (int kb = 0; kb < 8; ++kb) {
            float4 xr[4];
            #pragma unroll
            for (int i = 0; i < 4; ++i)
                xr[i] = *reinterpret_cast<const float4*>(xs + (4*g + i) * XST + kb*4);
            #pragma unroll
            for (int j = 0; j < 4; ++j) {
                int k = kb*4 + j;
                ulonglong2 wq = *reinterpret_cast<const ulonglong2*>(sm + WQ_OFF + k*32 + c4);
                ulonglong2 wk = *reinterpret_cast<const ulonglong2*>(sm + WK_OFF + k*32 + c4);
                ulonglong2 wv = *reinterpret_cast<const ulonglong2*>(sm + WV_OFF + k*32 + c4);
                #pragma unroll
                for (int i = 0; i < 4; ++i) {
                    float xv = f4c(xr[i], j);
                    u64 xx = pk2(xv, xv);
                    ffma2(aq[i*2], xx, wq.x); ffma2(aq[i*2+1], xx, wq.y);
                    ffma2(ak[i*2], xx, wk.x); ffma2(ak[i*2+1], xx, wk.y);
                    ffma2(av[i*2], xx, wv.x); ffma2(av[i*2+1], xx, wv.y);
                }
            }
        }
        {
            const float QSC = 0.17677669529663687f;  // 1/sqrt(D) folded into q
            #pragma unroll
            for (int i = 0; i < 4; ++i) {
                int r = 4*g + i;
                float a0, a1, a2, a3;
                upk2(aq[i*2], a0, a1); upk2(aq[i*2+1], a2, a3);
                *reinterpret_cast<float4*>(qs + r*QST + c4) =
                    make_float4(a0*QSC, a1*QSC, a2*QSC, a3*QSC);
                upk2(ak[i*2], a0, a1); upk2(ak[i*2+1], a2, a3);
                *reinterpret_cast<float4*>(ks + r*KST + c4) =
                    make_float4(a0, a1, a2, a3);
                upk2(av[i*2], a0, a1); upk2(av[i*2+1], a2, a3);
                *reinterpret_cast<float4*>(vs + r*VST + c4) =
                    make_float4(a0, a1, a2, a3);
            }
        }
        __syncwarp();

        // ===== scores[r][2m,2m+1] = q[r] . k[2m], q[r] . k[2m+1] =====
        u64 as_[4] = {0ull, 0ull, 0ull, 0ull};
        #pragma unroll
        for (int db = 0; db < 8; ++db) {
            float4 qr[4];
            #pragma unroll
            for (int i = 0; i < 4; ++i)
                qr[i] = *reinterpret_cast<const float4*>(qs + (4*g + i) * QST + db*4);
            float4 k0 = *reinterpret_cast<const float4*>(ks + (2*m    ) * KST + db*4);
            float4 k1 = *reinterpret_cast<const float4*>(ks + (2*m + 1) * KST + db*4);
            #pragma unroll
            for (int j = 0; j < 4; ++j) {
                u64 kk = pk2(f4c(k0, j), f4c(k1, j));
                #pragma unroll
                for (int i = 0; i < 4; ++i) {
                    float qv = f4c(qr[i], j);
                    ffma2(as_[i], pk2(qv, qv), kk);
                }
            }
        }
        // ---- softmax per row (8 m-lanes per row hold 16 scores) ----
        #pragma unroll
        for (int i = 0; i < 4; ++i) {
            float lo, hi; upk2(as_[i], lo, hi);
            float mx = fmaxf(lo, hi);
            #pragma unroll
            for (int o = 1; o < 8; o <<= 1)
                mx = fmaxf(mx, __shfl_xor_sync(0xffffffffu, mx, o));
            float e0 = __expf(lo - mx), e1 = __expf(hi - mx);
            float s = e0 + e1;
            #pragma unroll
            for (int o = 1; o < 8; o <<= 1)
                s += __shfl_xor_sync(0xffffffffu, s, o);
            float rs = __fdividef(1.0f, s);
            *reinterpret_cast<float2*>(ss + (4*g + i) * SST + 2*m) =
                make_float2(e0 * rs, e1 * rs);
        }
        __syncwarp();

        // ================= context = attn @ V  (-> qs) =================
        u64 ac[8];
        #pragma unroll
        for (int i = 0; i < 8; ++i) ac[i] = 0ull;
        #pragma unroll
        for (int tb = 0; tb < 4; ++tb) {
            float4 ar[4];
            #pragma unroll
            for (int i = 0; i < 4; ++i)
                ar[i] = *reinterpret_cast<const float4*>(ss + (4*g + i) * SST + tb*4);
            #pragma unroll
            for (int j = 0; j < 4; ++j) {
                int t = tb*4 + j;
                ulonglong2 vv = *reinterpret_cast<const ulonglong2*>(vs + t*VST + c4);
                #pragma unroll
                for (int i = 0; i < 4; ++i) {
                    float a = f4c(ar[i], j);
                    u64 aa = pk2(a, a);
                    ffma2(ac[i*2], aa, vv.x); ffma2(ac[i*2+1], aa, vv.y);
                }
            }
        }
        #pragma unroll
        for (int i = 0; i < 4; ++i) {
            int r = 4*g + i;
            float a0, a1, a2, a3;
            upk2(ac[i*2], a0, a1); upk2(ac[i*2+1], a2, a3);
            *reinterpret_cast<float4*>(qs + r*QST + c4) = make_float4(a0, a1, a2, a3);
        }
        __syncwarp();

        // ================= y = x + ctx @ Wo + bo  (-> xs) =================
        u64 ay[8];
        {
            ulonglong2 b_o = *reinterpret_cast<const ulonglong2*>(sm + BO_OFF + c4);
            #pragma unroll
            for (int i = 0; i < 4; ++i) { ay[i*2] = b_o.x; ay[i*2+1] = b_o.y; }
        }
        #pragma unroll
        for (int kb = 0; kb < 8; ++kb) {
            float4 cr[4];
            #pragma unroll
            for (int i = 0; i < 4; ++i)
                cr[i] = *reinterpret_cast<const float4*>(qs + (4*g + i) * QST + kb*4);
            #pragma unroll
            for (int j = 0; j < 4; ++j) {
                int k = kb*4 + j;
                ulonglong2 w = *reinterpret_cast<const ulonglong2*>(sm + WO_OFF + k*32 + c4);
                #pragma unroll
                for (int i = 0; i < 4; ++i) {
                    float cv = f4c(cr[i], j);
                    u64 cc = pk2(cv, cv);
                    ffma2(ay[i*2], cc, w.x); ffma2(ay[i*2+1], cc, w.y);
                }
            }
        }
        #pragma unroll
        for (int i = 0; i < 4; ++i) {
            int r = 4*g + i;
            float4 x4 = *reinterpret_cast<const float4*>(xs + r*XST + c4);
            float a0, a1, a2, a3;
            upk2(ay[i*2], a0, a1); upk2(ay[i*2+1], a2, a3);
            *reinterpret_cast<float4*>(xs + r*XST + c4) =
                make_float4(a0 + x4.x, a1 + x4.y, a2 + x4.z, a3 + x4.w);
        }
        __syncwarp();

        // ================= h = relu(y @ W1 + b1)  (-> hs) =================
        u64 ah[16];
        {
            ulonglong2 b1a = *reinterpret_cast<const ulonglong2*>(sm + B1_OFF + c8);
            ulonglong2 b1b = *reinterpret_cast<const ulonglong2*>(sm + B1_OFF + c8 + 4);
            #pragma unroll
            for (int i = 0; i < 4; ++i) {
                ah[i*4]   = b1a.x; ah[i*4+1] = b1a.y;
                ah[i*4+2] = b1b.x; ah[i*4+3] = b1b.y;
            }
        }
        #pragma unroll
        for (int kb = 0; kb < 8; ++kb) {
            float4 yr[4];
            #pragma unroll
            for (int i = 0; i < 4; ++i)
                yr[i] = *reinterpret_cast<const float4*>(xs + (4*g + i) * XST + kb*4);
            #pragma unroll
            for (int j = 0; j < 4; ++j) {
                int k = kb*4 + j;
                ulonglong2 w1a = *reinterpret_cast<const ulonglong2*>(sm + W1_OFF + k*64 + c8);
                ulonglong2 w1b = *reinterpret_cast<const ulonglong2*>(sm + W1_OFF + k*64 + c8 + 4);
                #pragma unroll
                for (int i = 0; i < 4; ++i) {
                    float yv = f4c(yr[i], j);
                    u64 xx = pk2(yv, yv);
                    ffma2(ah[i*4],   xx, w1a.x); ffma2(ah[i*4+1], xx, w1a.y);
                    ffma2(ah[i*4+2], xx, w1b.x); ffma2(ah[i*4+3], xx, w1b.y);
                }
            }
        }
        #pragma unroll
        for (int i = 0; i < 4; ++i) {
            int r = 4*g + i;
            float a0, a1, a2, a3, a4, a5, a6, a7;
            upk2(ah[i*4],   a0, a1); upk2(ah[i*4+1], a2, a3);
            upk2(ah[i*4+2], a4, a5); upk2(ah[i*4+3], a6, a7);
            *reinterpret_cast<float4*>(hs + r*HST + c8) =
                make_float4(fmaxf(a0,0.f), fmaxf(a1,0.f), fmaxf(a2,0.f), fmaxf(a3,0.f));
            *reinterpret_cast<float4*>(hs + r*HST + c8 + 4) =
                make_float4(fmaxf(a4,0.f), fmaxf(a5,0.f), fmaxf(a6,0.f), fmaxf(a7,0.f));
        }
        __syncwarp();

        // ================= z = y + h @ W2 + b2  (-> gmem) =================
        u64 az[8];
        {
            ulonglong2 b_2 = *reinterpret_cast<const ulonglong2*>(sm + B2_OFF + c4);
            #pragma unroll
            for (int i = 0; i < 4; ++i) { az[i*2] = b_2.x; az[i*2+1] = b_2.y; }
        }
        #pragma unroll
        for (int kb = 0; kb < 16; ++kb) {
            float4 hr[4];
            #pragma unroll
            for (int i = 0; i < 4; ++i)
                hr[i] = *reinterpret_cast<const float4*>(hs + (4*g + i) * HST + kb*4);
            #pragma unroll
            for (int j = 0; j < 4; ++j) {
                int k = kb*4 + j;
                ulonglong2 w = *reinterpret_cast<const ulonglong2*>(sm + W2_OFF + k*32 + c4);
                #pragma unroll
                for (int i = 0; i < 4; ++i) {
                    float hv = f4c(hr[i], j);
                    u64 hh = pk2(hv, hv);
                    ffma2(az[i*2], hh, w.x); ffma2(az[i*2+1], hh, w.y);
                }
            }
        }
        {
            float* ob = gout + (size_t)b * 512;
            #pragma unroll
            for (int i = 0; i < 4; ++i) {
                int r = 4*g + i;
                float4 yr = *reinterpret_cast<const float4*>(xs + r*XST + c4);
                float z0, z1, z2, z3;
                upk2(az[i*2], z0, z1); upk2(az[i*2+1], z2, z3);
                float4 o;
                o.x = z0 + yr.x; o.y = z1 + yr.y; o.z = z2 + yr.z; o.w = z3 + yr.w;
                *reinterpret_cast<float4*>(ob + r*32 + c4) = o;
            }
        }
        __syncwarp();   // protect scratch before next item's overwrite
    }
}

extern "C" void kernel_launch(void* const* d_in, const int* in_sizes, int n_in,
                              void* d_out, int out_size)
{
    const float* x  = (const float*)d_in[0];
    const float* Wq = (const float*)d_in[1];
    const float* bq = (const float*)d_in[2];
    const float* Wk = (const float*)d_in[3];
    const float* bk = (const float*)d_in[4];
    const float* Wv = (const float*)d_in[5];
    const float* bv = (const float*)d_in[6];
    const float* Wo = (const float*)d_in[7];
    const float* bo = (const float*)d_in[8];
    const float* W1 = (const float*)d_in[9];
    const float* b1 = (const float*)d_in[10];
    const float* W2 = (const float*)d_in[11];
    const float* b2 = (const float*)d_in[12];
    float* out = (float*)d_out;

    const size_t smem = SMEM_FLOATS * sizeof(float);  // 96640 B
    cudaFuncSetAttribute(tformer_kernel,
                         cudaFuncAttributeMaxDynamicSharedMemorySize, (int)smem);

    tformer_kernel<<<NBLK, NTHR, smem>>>(x, Wq, bq, Wk, bk, Wv, bv, Wo, bo,
                                         W1, b1, W2, b2, out);
}